// round 16
// baseline (speedup 1.0000x reference)
#include <cuda_runtime.h>
#include <cuda_bf16.h>
#include <math.h>

// Problem constants
#define BATCH   2
#define S_LEN   2048
#define DIM     1024
#define N_HEADS 16
#define HEAD_D  64
#define D3      (3 * DIM)
#define MROWS   (BATCH * S_LEN)   // 4096

// Scratch (device globals: allocation-free per harness rules)
__device__ float g_qkv[(size_t)MROWS * D3];    // [4096, 3072]  Q | K | V
__device__ float g_attn[(size_t)MROWS * DIM];  // [4096, 1024]  attention output

// ============================================================================
// SGEMM with bias:  C[M,N] = A[M,K] @ W[N,K]^T + bias[N]
// 128x128 block tile, BK=16, 256 threads, 8x8 micro-tile.
// ============================================================================
#define BM 128
#define BN 128
#define BK 16
#define SPAD 4

__global__ __launch_bounds__(256)
void sgemm_bias_kernel(const float* __restrict__ A, const float* __restrict__ W,
                       const float* __restrict__ bias, float* __restrict__ C,
                       int M, int N, int K)
{
    __shared__ float As[BK][BM + SPAD];
    __shared__ float Ws[BK][BN + SPAD];

    const int tid = threadIdx.x;
    const int tr  = tid >> 4;    // 0..15 (row group)
    const int tc  = tid & 15;    // 0..15 (col group)
    const int m0  = blockIdx.y * BM;
    const int n0  = blockIdx.x * BN;

    float acc[8][8];
#pragma unroll
    for (int i = 0; i < 8; ++i)
#pragma unroll
        for (int j = 0; j < 8; ++j) acc[i][j] = 0.0f;

    for (int k0 = 0; k0 < K; k0 += BK) {
        __syncthreads();
        // Load A and W tiles (128 rows x 16 k), transposed into smem.
        // 512 float4 per tile, 2 per thread.
#pragma unroll
        for (int i = 0; i < 2; ++i) {
            int f   = tid + i * 256;       // 0..511
            int row = f >> 2;              // 0..127
            int kq  = (f & 3) * 4;         // 0,4,8,12
            float4 a = *(const float4*)(A + (size_t)(m0 + row) * K + k0 + kq);
            As[kq + 0][row] = a.x;
            As[kq + 1][row] = a.y;
            As[kq + 2][row] = a.z;
            As[kq + 3][row] = a.w;
            float4 w = *(const float4*)(W + (size_t)(n0 + row) * K + k0 + kq);
            Ws[kq + 0][row] = w.x;
            Ws[kq + 1][row] = w.y;
            Ws[kq + 2][row] = w.z;
            Ws[kq + 3][row] = w.w;
        }
        __syncthreads();

#pragma unroll
        for (int kk = 0; kk < BK; ++kk) {
            float a[8], b[8];
            *(float4*)&a[0] = *(const float4*)&As[kk][tr * 8];
            *(float4*)&a[4] = *(const float4*)&As[kk][tr * 8 + 4];
            *(float4*)&b[0] = *(const float4*)&Ws[kk][tc * 8];
            *(float4*)&b[4] = *(const float4*)&Ws[kk][tc * 8 + 4];
#pragma unroll
            for (int i = 0; i < 8; ++i)
#pragma unroll
                for (int j = 0; j < 8; ++j)
                    acc[i][j] = fmaf(a[i], b[j], acc[i][j]);
        }
    }

    // Epilogue: add bias, float4 stores
#pragma unroll
    for (int i = 0; i < 8; ++i) {
        int m = m0 + tr * 8 + i;
#pragma unroll
        for (int j = 0; j < 8; j += 4) {
            int n = n0 + tc * 8 + j;
            float4 r;
            r.x = acc[i][j + 0] + bias[n + 0];
            r.y = acc[i][j + 1] + bias[n + 1];
            r.z = acc[i][j + 2] + bias[n + 2];
            r.w = acc[i][j + 3] + bias[n + 3];
            *(float4*)(C + (size_t)m * N + n) = r;
        }
    }
}

// ============================================================================
// Flash attention (fp32, online softmax).
// One block per (q-tile of 64 rows, head, batch). 256 threads = 16x16,
// each thread owns a 4x4 micro-tile of the 64x64 S tile and the 64x64 O tile.
// Smem (dynamic, 69632 B): Qs/Ks stored d-major [64][68], Vs key-major
// [64][68], Ps key-major [64][68].
// ============================================================================
#define LDX 68   // smem row stride (multiple of 4 for float4 alignment)

__global__ __launch_bounds__(256)
void flash_kernel(const float* __restrict__ qkv, float* __restrict__ attn_out)
{
    extern __shared__ float sm[];
    float* Qs = sm;                 // Qs[d][r]
    float* Ks = sm + 64 * LDX;      // Ks[d][c]
    float* Vs = sm + 2 * 64 * LDX;  // Vs[k][d]
    float* Ps = sm + 3 * 64 * LDX;  // Ps[k][r]

    const int tid = threadIdx.x;
    const int tr  = tid >> 4;       // 0..15
    const int tc  = tid & 15;       // 0..15
    const int q0  = blockIdx.x * 64;
    const int h   = blockIdx.y;
    const int b   = blockIdx.z;

    const float* base = qkv + (size_t)b * S_LEN * D3;
    const int lr = tid >> 6;        // 0..3
    const int ld = tid & 63;        // 0..63

    // Load Q tile, transposed: Qs[d][r]
#pragma unroll
    for (int it = 0; it < 16; ++it) {
        int r = it * 4 + lr;
        Qs[ld * LDX + r] = base[(size_t)(q0 + r) * D3 + h * HEAD_D + ld];
    }

    float m_i[4], l_i[4], o[4][4];
#pragma unroll
    for (int i = 0; i < 4; ++i) {
        m_i[i] = -1e30f;
        l_i[i] = 0.0f;
#pragma unroll
        for (int j = 0; j < 4; ++j) o[i][j] = 0.0f;
    }

    const float scale = 0.125f;  // 1/sqrt(64)

    for (int k0 = 0; k0 < S_LEN; k0 += 64) {
        __syncthreads();  // previous tile's phase-3 reads of Ks/Vs/Ps done
        // Load K (transposed, d-major) and V (key-major)
#pragma unroll
        for (int it = 0; it < 16; ++it) {
            int r = it * 4 + lr;
            Ks[ld * LDX + r] = base[(size_t)(k0 + r) * D3 + DIM     + h * HEAD_D + ld];
            Vs[r * LDX + ld] = base[(size_t)(k0 + r) * D3 + 2 * DIM + h * HEAD_D + ld];
        }
        __syncthreads();

        // Phase 1: S = Q @ K^T  (64x64x64)
        float s[4][4];
#pragma unroll
        for (int i = 0; i < 4; ++i)
#pragma unroll
            for (int j = 0; j < 4; ++j) s[i][j] = 0.0f;

#pragma unroll 8
        for (int kk = 0; kk < 64; ++kk) {
            float4 a  = *(const float4*)(Qs + kk * LDX + tr * 4);
            float4 bb = *(const float4*)(Ks + kk * LDX + tc * 4);
            float av[4] = {a.x, a.y, a.z, a.w};
            float bv[4] = {bb.x, bb.y, bb.z, bb.w};
#pragma unroll
            for (int i = 0; i < 4; ++i)
#pragma unroll
                for (int j = 0; j < 4; ++j)
                    s[i][j] = fmaf(av[i], bv[j], s[i][j]);
        }

        // Phase 2: online softmax (row reductions across the 16-lane tc group)
#pragma unroll
        for (int i = 0; i < 4; ++i) {
#pragma unroll
            for (int j = 0; j < 4; ++j) s[i][j] *= scale;
            float mt = fmaxf(fmaxf(s[i][0], s[i][1]), fmaxf(s[i][2], s[i][3]));
#pragma unroll
            for (int off = 8; off > 0; off >>= 1)
                mt = fmaxf(mt, __shfl_xor_sync(0xffffffffu, mt, off, 16));
            float mnew  = fmaxf(m_i[i], mt);
            float alpha = __expf(m_i[i] - mnew);
            m_i[i] = mnew;
            float rs = 0.0f;
#pragma unroll
            for (int j = 0; j < 4; ++j) {
                float p = __expf(s[i][j] - mnew);
                s[i][j] = p;
                rs += p;
            }
#pragma unroll
            for (int off = 8; off > 0; off >>= 1)
                rs += __shfl_xor_sync(0xffffffffu, rs, off, 16);
            l_i[i] = l_i[i] * alpha + rs;
#pragma unroll
            for (int j = 0; j < 4; ++j) o[i][j] *= alpha;
        }

        // Stage P (key-major) in smem for the PV GEMM
#pragma unroll
        for (int i = 0; i < 4; ++i)
#pragma unroll
            for (int j = 0; j < 4; ++j)
                Ps[(tc * 4 + j) * LDX + tr * 4 + i] = s[i][j];
        __syncthreads();

        // Phase 3: O += P @ V  (64x64x64)
#pragma unroll 8
        for (int kk = 0; kk < 64; ++kk) {
            float4 p = *(const float4*)(Ps + kk * LDX + tr * 4);
            float4 v = *(const float4*)(Vs + kk * LDX + tc * 4);
            float pv[4] = {p.x, p.y, p.z, p.w};
            float vv[4] = {v.x, v.y, v.z, v.w};
#pragma unroll
            for (int i = 0; i < 4; ++i)
#pragma unroll
                for (int j = 0; j < 4; ++j)
                    o[i][j] = fmaf(pv[i], vv[j], o[i][j]);
        }
    }

    // Epilogue: normalize and write [b, s, h*64 + d] layout
#pragma unroll
    for (int i = 0; i < 4; ++i) {
        float inv = 1.0f / l_i[i];
        int row = q0 + tr * 4 + i;
        float4 r;
        r.x = o[i][0] * inv;
        r.y = o[i][1] * inv;
        r.z = o[i][2] * inv;
        r.w = o[i][3] * inv;
        *(float4*)(attn_out + ((size_t)b * S_LEN + row) * DIM + h * HEAD_D + tc * 4) = r;
    }
}

// ============================================================================
// Launch
// ============================================================================
extern "C" void kernel_launch(void* const* d_in, const int* in_sizes, int n_in,
                              void* d_out, int out_size)
{
    const float* x      = (const float*)d_in[0];
    const float* w_qkv  = (const float*)d_in[1];
    const float* b_qkv  = (const float*)d_in[2];
    const float* w_proj = (const float*)d_in[3];
    const float* b_proj = (const float*)d_in[4];
    float* out = (float*)d_out;

    float* qkv;  cudaGetSymbolAddress((void**)&qkv,  g_qkv);
    float* attn; cudaGetSymbolAddress((void**)&attn, g_attn);

    const int flash_smem = 4 * 64 * LDX * (int)sizeof(float);  // 69632 B
    cudaFuncSetAttribute(flash_kernel,
                         cudaFuncAttributeMaxDynamicSharedMemorySize, flash_smem);

    dim3 blk(256);

    // 1) QKV projection: [4096,1024] @ [3072,1024]^T + b -> [4096,3072]
    sgemm_bias_kernel<<<dim3(D3 / BN, MROWS / BM), blk>>>(
        x, w_qkv, b_qkv, qkv, MROWS, D3, DIM);

    // 2) Attention per (q-tile, head, batch)
    flash_kernel<<<dim3(S_LEN / 64, N_HEADS, BATCH), blk, flash_smem>>>(qkv, attn);

    // 3) Output projection: [4096,1024] @ [1024,1024]^T + b -> d_out
    sgemm_bias_kernel<<<dim3(DIM / BN, MROWS / BM), blk>>>(
        attn, w_proj, b_proj, out, MROWS, DIM, DIM);
}

// round 17
// speedup vs baseline: 1.0825x; 1.0825x over previous
#include <cuda_runtime.h>
#include <cuda_bf16.h>
#include <mma.h>
#include <math.h>

using namespace nvcuda;

// Problem constants
#define BATCH   2
#define S_LEN   2048
#define DIM     1024
#define N_HEADS 16
#define HEAD_D  64
#define D3      (3 * DIM)
#define MROWS   (BATCH * S_LEN)   // 4096

// Scratch (device globals: allocation-free per harness rules)
__device__ float g_qkv[(size_t)MROWS * D3];    // [4096, 3072]  Q | K | V
__device__ float g_attn[(size_t)MROWS * DIM];  // [4096, 1024]  attention output

// Round all elements of a wmma fragment to tf32 (cvt.rna)
template <typename Frag>
__device__ __forceinline__ void frag_to_tf32(Frag& f) {
#pragma unroll
    for (int i = 0; i < f.num_elements; ++i)
        f.x[i] = wmma::__float_to_tf32(f.x[i]);
}

// ============================================================================
// tf32 GEMM with bias:  C[M,N] = A[M,K] @ W[N,K]^T + bias[N]
// Block tile 128x128, BK=16, 256 threads = 8 warps (4 warp-rows x 2 warp-cols),
// warp tile 32x64 = 2x4 fragments of 16x16. fp32 accumulation.
// ============================================================================
#define GBK   16
#define GLDA  20    // smem stride for A/W tiles (16 + 4 pad, multiple of 4)
#define GLDC  132   // smem stride for epilogue staging

__global__ __launch_bounds__(256)
void gemm_tf32(const float* __restrict__ A, const float* __restrict__ W,
               const float* __restrict__ bias, float* __restrict__ C,
               int M, int N, int K)
{
    extern __shared__ float smem[];
    float* As = smem;               // [128][GLDA]
    float* Ws = smem + 128 * GLDA;  // [128][GLDA]

    const int tid  = threadIdx.x;
    const int warp = tid >> 5;
    const int wr   = warp & 3;      // 0..3 warp row
    const int wc   = warp >> 2;     // 0..1 warp col
    const int m0   = blockIdx.y * 128;
    const int n0   = blockIdx.x * 128;

    wmma::fragment<wmma::accumulator, 16, 16, 8, float> c[2][4];
#pragma unroll
    for (int mi = 0; mi < 2; ++mi)
#pragma unroll
        for (int ni = 0; ni < 4; ++ni)
            wmma::fill_fragment(c[mi][ni], 0.0f);

    for (int k0 = 0; k0 < K; k0 += GBK) {
        __syncthreads();
        // Load 128x16 tiles of A and W (row-major). 512 float4 each, 2/thread.
#pragma unroll
        for (int i = 0; i < 2; ++i) {
            int f   = tid + i * 256;       // 0..511
            int row = f >> 2;              // 0..127
            int kq  = (f & 3) * 4;         // 0,4,8,12
            float4 a = *(const float4*)(A + (size_t)(m0 + row) * K + k0 + kq);
            *(float4*)&As[row * GLDA + kq] = a;
            float4 w = *(const float4*)(W + (size_t)(n0 + row) * K + k0 + kq);
            *(float4*)&Ws[row * GLDA + kq] = w;
        }
        __syncthreads();

#pragma unroll
        for (int ks = 0; ks < GBK; ks += 8) {
            wmma::fragment<wmma::matrix_a, 16, 16, 8, wmma::precision::tf32,
                           wmma::row_major> a[2];
            wmma::fragment<wmma::matrix_b, 16, 16, 8, wmma::precision::tf32,
                           wmma::col_major> b[4];
#pragma unroll
            for (int mi = 0; mi < 2; ++mi) {
                wmma::load_matrix_sync(a[mi],
                    &As[(wr * 32 + mi * 16) * GLDA + ks], GLDA);
                frag_to_tf32(a[mi]);
            }
#pragma unroll
            for (int ni = 0; ni < 4; ++ni) {
                // B(k,n) = W[n0c + n][k] = Ws[(n)*GLDA + k] -> col_major ldb=GLDA
                wmma::load_matrix_sync(b[ni],
                    &Ws[(wc * 64 + ni * 16) * GLDA + ks], GLDA);
                frag_to_tf32(b[ni]);
            }
#pragma unroll
            for (int mi = 0; mi < 2; ++mi)
#pragma unroll
                for (int ni = 0; ni < 4; ++ni)
                    wmma::mma_sync(c[mi][ni], a[mi], b[ni], c[mi][ni]);
        }
    }

    // Epilogue: stage C in smem (aliases As/Ws), add bias, coalesced stores.
    __syncthreads();
    float* cbuf = smem;  // [128][GLDC]
#pragma unroll
    for (int mi = 0; mi < 2; ++mi)
#pragma unroll
        for (int ni = 0; ni < 4; ++ni)
            wmma::store_matrix_sync(
                &cbuf[(wr * 32 + mi * 16) * GLDC + wc * 64 + ni * 16],
                c[mi][ni], GLDC, wmma::mem_row_major);
    __syncthreads();

#pragma unroll
    for (int i = 0; i < 16; ++i) {
        int f   = tid + i * 256;       // 0..4095
        int row = f >> 5;              // 0..127
        int c4  = (f & 31) * 4;        // 0..124
        float4 v = *(float4*)&cbuf[row * GLDC + c4];
        const float4 bb = *(const float4*)(bias + n0 + c4);
        v.x += bb.x; v.y += bb.y; v.z += bb.z; v.w += bb.w;
        *(float4*)(C + (size_t)(m0 + row) * N + n0 + c4) = v;
    }
}

// ============================================================================
// Flash attention, tf32 tensor cores, fp32 softmax/accumulation.
// One block per (64-row q-tile, head, batch); 128 threads = 4 warps.
// Warp w owns q-rows [w*16, w*16+16) x all 64 key-cols / 64 d-cols.
// S staged in smem for softmax; O lives in smem, rescaled by alpha per row,
// and round-trips through wmma accumulator load/store for the PV MMA.
// ============================================================================
#define FS 68   // smem row stride (64 + 4, multiple of 4)

__global__ __launch_bounds__(128)
void flash_tf32(const float* __restrict__ qkv, float* __restrict__ attn_out)
{
    extern __shared__ float sm[];
    float* Qs  = sm;              // [64][FS]  Q[r][d]
    float* Ks  = Qs + 64 * FS;    // [64][FS]  K[kcol][d]
    float* Vs  = Ks + 64 * FS;    // [64][FS]  V[k][d]
    float* Ss  = Vs + 64 * FS;    // [64][FS]  S / P
    float* Os  = Ss + 64 * FS;    // [64][FS]  O accumulator
    float* m_s = Os + 64 * FS;    // [64]
    float* l_s = m_s + 64;        // [64]

    const int tid  = threadIdx.x;
    const int warp = tid >> 5;
    const int q0   = blockIdx.x * 64;
    const int h    = blockIdx.y;
    const int b    = blockIdx.z;
    const float* base = qkv + (size_t)b * S_LEN * D3;

    // Load Q tile + init O/m/l
#pragma unroll
    for (int i = 0; i < 8; ++i) {
        int f   = tid + i * 128;   // 0..1023
        int row = f >> 4;          // 0..63
        int c4  = (f & 15) * 4;    // 0..60
        *(float4*)&Qs[row * FS + c4] =
            *(const float4*)&base[(size_t)(q0 + row) * D3 + h * HEAD_D + c4];
        *(float4*)&Os[row * FS + c4] = make_float4(0.f, 0.f, 0.f, 0.f);
    }
    if (tid < 64) { m_s[tid] = -1e30f; l_s[tid] = 0.0f; }

    const int m0 = warp * 16;
    const float scale = 0.125f;   // 1/sqrt(64)

    for (int k0 = 0; k0 < S_LEN; k0 += 64) {
        __syncthreads();
        // Load K (d-contiguous) and V (d-contiguous)
#pragma unroll
        for (int i = 0; i < 8; ++i) {
            int f   = tid + i * 128;
            int row = f >> 4;
            int c4  = (f & 15) * 4;
            *(float4*)&Ks[row * FS + c4] = *(const float4*)
                &base[(size_t)(k0 + row) * D3 + DIM + h * HEAD_D + c4];
            *(float4*)&Vs[row * FS + c4] = *(const float4*)
                &base[(size_t)(k0 + row) * D3 + 2 * DIM + h * HEAD_D + c4];
        }
        __syncthreads();

        // ---- QK^T: S[m0..m0+15][0..63] ----
        {
            wmma::fragment<wmma::accumulator, 16, 16, 8, float> cf[4];
#pragma unroll
            for (int n = 0; n < 4; ++n) wmma::fill_fragment(cf[n], 0.0f);
#pragma unroll
            for (int ks = 0; ks < 8; ++ks) {
                wmma::fragment<wmma::matrix_a, 16, 16, 8, wmma::precision::tf32,
                               wmma::row_major> af;
                wmma::load_matrix_sync(af, &Qs[m0 * FS + ks * 8], FS);
                frag_to_tf32(af);
#pragma unroll
                for (int n = 0; n < 4; ++n) {
                    // B(k,n) = K[n][k] -> col_major at &Ks[n0*FS + ks*8], ldb=FS
                    wmma::fragment<wmma::matrix_b, 16, 16, 8,
                                   wmma::precision::tf32, wmma::col_major> bf;
                    wmma::load_matrix_sync(bf, &Ks[(n * 16) * FS + ks * 8], FS);
                    frag_to_tf32(bf);
                    wmma::mma_sync(cf[n], af, bf, cf[n]);
                }
            }
#pragma unroll
            for (int n = 0; n < 4; ++n)
                wmma::store_matrix_sync(&Ss[m0 * FS + n * 16], cf[n], FS,
                                        wmma::mem_row_major);
        }
        __syncthreads();

        // ---- Online softmax: 2 threads per row (shfl partner = lane^1) ----
        {
            const int r  = tid >> 1;
            const int c0 = (tid & 1) * 32;
            float mold = m_s[r];
            float lold = l_s[r];
            float vals[32];
            float pm = -1e30f;
#pragma unroll
            for (int j = 0; j < 32; ++j) {
                vals[j] = Ss[r * FS + c0 + j] * scale;
                pm = fmaxf(pm, vals[j]);
            }
            pm = fmaxf(pm, __shfl_xor_sync(0xffffffffu, pm, 1));
            float mnew  = fmaxf(mold, pm);
            float alpha = __expf(mold - mnew);
            float ps = 0.0f;
#pragma unroll
            for (int j = 0; j < 32; ++j) {
                float p = __expf(vals[j] - mnew);
                Ss[r * FS + c0 + j] = p;
                ps += p;
            }
            ps += __shfl_xor_sync(0xffffffffu, ps, 1);
            if ((tid & 1) == 0) {
                m_s[r] = mnew;
                l_s[r] = lold * alpha + ps;
            }
            // Rescale O row by alpha
#pragma unroll
            for (int j = 0; j < 32; ++j)
                Os[r * FS + c0 + j] *= alpha;
        }
        __syncthreads();

        // ---- PV: O[m0..m0+15][0..63] += P @ V ----
        {
            wmma::fragment<wmma::accumulator, 16, 16, 8, float> of[4];
#pragma unroll
            for (int n = 0; n < 4; ++n)
                wmma::load_matrix_sync(of[n], &Os[m0 * FS + n * 16], FS,
                                       wmma::mem_row_major);
#pragma unroll
            for (int ks = 0; ks < 8; ++ks) {
                wmma::fragment<wmma::matrix_a, 16, 16, 8, wmma::precision::tf32,
                               wmma::row_major> af;
                wmma::load_matrix_sync(af, &Ss[m0 * FS + ks * 8], FS);
                frag_to_tf32(af);
#pragma unroll
                for (int n = 0; n < 4; ++n) {
                    // B(k,d) = V[k][d] -> row_major at &Vs[ks*8*FS + n*16]
                    wmma::fragment<wmma::matrix_b, 16, 16, 8,
                                   wmma::precision::tf32, wmma::row_major> bf;
                    wmma::load_matrix_sync(bf, &Vs[(ks * 8) * FS + n * 16], FS);
                    frag_to_tf32(bf);
                    wmma::mma_sync(of[n], af, bf, of[n]);
                }
            }
#pragma unroll
            for (int n = 0; n < 4; ++n)
                wmma::store_matrix_sync(&Os[m0 * FS + n * 16], of[n], FS,
                                        wmma::mem_row_major);
        }
    }
    __syncthreads();

    // Epilogue: normalize by 1/l, write [b, s, h*64+d]
    {
        const int r  = tid >> 1;
        const int c0 = (tid & 1) * 32;
        const float inv = 1.0f / l_s[r];
        float* dst = attn_out + ((size_t)b * S_LEN + q0 + r) * DIM
                   + h * HEAD_D + c0;
#pragma unroll
        for (int j = 0; j < 32; j += 4) {
            float4 v = *(float4*)&Os[r * FS + c0 + j];
            v.x *= inv; v.y *= inv; v.z *= inv; v.w *= inv;
            *(float4*)(dst + j) = v;
        }
    }
}

// ============================================================================
// Launch
// ============================================================================
extern "C" void kernel_launch(void* const* d_in, const int* in_sizes, int n_in,
                              void* d_out, int out_size)
{
    const float* x      = (const float*)d_in[0];
    const float* w_qkv  = (const float*)d_in[1];
    const float* b_qkv  = (const float*)d_in[2];
    const float* w_proj = (const float*)d_in[3];
    const float* b_proj = (const float*)d_in[4];
    float* out = (float*)d_out;

    float* qkv;  cudaGetSymbolAddress((void**)&qkv,  g_qkv);
    float* attn; cudaGetSymbolAddress((void**)&attn, g_attn);

    const int gemm_smem  = 128 * GLDC * (int)sizeof(float);          // 67584 B
    const int flash_smem = (5 * 64 * FS + 128) * (int)sizeof(float); // 87552 B
    cudaFuncSetAttribute(gemm_tf32,
                         cudaFuncAttributeMaxDynamicSharedMemorySize, gemm_smem);
    cudaFuncSetAttribute(flash_tf32,
                         cudaFuncAttributeMaxDynamicSharedMemorySize, flash_smem);

    // 1) QKV projection: [4096,1024] @ [3072,1024]^T + b -> [4096,3072]
    gemm_tf32<<<dim3(D3 / 128, MROWS / 128), 256, gemm_smem>>>(
        x, w_qkv, b_qkv, qkv, MROWS, D3, DIM);

    // 2) Flash attention
    flash_tf32<<<dim3(S_LEN / 64, N_HEADS, BATCH), 128, flash_smem>>>(qkv, attn);

    // 3) Output projection: [4096,1024] @ [1024,1024]^T + b -> d_out
    gemm_tf32<<<dim3(DIM / 128, MROWS / 128), 256, gemm_smem>>>(
        attn, w_proj, b_proj, out, MROWS, DIM, DIM);
}